// round 1
// baseline (speedup 1.0000x reference)
#include <cuda_runtime.h>
#include <cuda_bf16.h>
#include <cstdint>

// Problem constants
#define BATCH 32
#define SEQ   1024
#define HID   1024
#define WIN   128          // windows per batch
#define KSUB  6            // subtokens per window
#define NHEAD 16
#define HD    64
#define NWIN  (BATCH * WIN)        // 4096 total windows
#define NROWS (NWIN * KSUB)        // 24576 gathered rows

// GEMM tiling
#define WT_PER_BLK 16              // windows per block
#define MT (WT_PER_BLK * KSUB)     // 96 rows
#define NT 128                     // 64 q cols + 64 k cols (one head)
#define KC 32                      // k chunk

#define SA_STRIDE 36
#define SB_STRIDE 36
#define SQK_STRIDE 133
// smem layout (floats):
//   phase1: sA [96*36] @0, sB [128*36] @3456   (ends at 8064)
//   phase2: sQK [96*133] @0                    (12768)
//   sAT [96*6=576] @12768 ; sMask [16 ints] @13344
#define SMEM_FLOATS (96 * SQK_STRIDE + 96 * 6 + 16)
#define SMEM_BYTES  (SMEM_FLOATS * 4)

// Scratch (static device globals — no allocation)
__device__ float g_X[(size_t)NROWS * HID];          // gathered, masked subtoken rows (fp32)
__device__ float g_contribH[NHEAD * NROWS];         // per-head contrib partials

__device__ __forceinline__ float to_tf32(float x) {
    uint32_t u;
    asm("cvt.rna.tf32.f32 %0, %1;" : "=r"(u) : "f"(x));
    return __uint_as_float(u);
}

__device__ __forceinline__ void mma_tf32(float c[4], uint32_t a0, uint32_t a1,
                                         uint32_t a2, uint32_t a3,
                                         uint32_t b0, uint32_t b1) {
    asm volatile(
        "mma.sync.aligned.m16n8k8.row.col.f32.tf32.tf32.f32 "
        "{%0,%1,%2,%3}, {%4,%5,%6,%7}, {%8,%9}, {%0,%1,%2,%3};\n"
        : "+f"(c[0]), "+f"(c[1]), "+f"(c[2]), "+f"(c[3])
        : "r"(a0), "r"(a1), "r"(a2), "r"(a3), "r"(b0), "r"(b1));
}

// ---------------------------------------------------------------------------
// Kernel 1: gather masked subtoken rows into g_X (fp32). One block per row.
// valid(bw,k) = idx!=0 || (w==0 && k==0)   [reconstructs subtok_mask exactly]
// ---------------------------------------------------------------------------
__global__ void __launch_bounds__(256)
gather_kernel(const float* __restrict__ emb, const int* __restrict__ idx) {
    int row = blockIdx.x;                 // 0..24575 = bw*6 + k
    int t = threadIdx.x;                  // 0..255 (float4 columns)
    int bw = row / KSUB;
    int k = row - bw * KSUB;
    int id = idx[row];
    bool valid = (id != 0) || (((bw & (WIN - 1)) == 0) && (k == 0));
    int b = bw >> 7;                      // bw / WIN
    float4 v = make_float4(0.f, 0.f, 0.f, 0.f);
    if (valid) {
        v = reinterpret_cast<const float4*>(emb)[(size_t)(b * SEQ + id) * (HID / 4) + t];
    }
    reinterpret_cast<float4*>(g_X)[(size_t)row * (HID / 4) + t] = v;
}

// ---------------------------------------------------------------------------
// Kernel 2: passthrough with zeroing of covered positions.
// ---------------------------------------------------------------------------
__global__ void __launch_bounds__(256)
passthrough_kernel(const float* __restrict__ emb, const int* __restrict__ idx,
                   float* __restrict__ out) {
    int gid = blockIdx.x * 256 + threadIdx.x;     // float4 index, 8388608 total
    int sg = gid >> 8;                            // b*SEQ + s
    int b = sg >> 10;
    int s = sg & (SEQ - 1);
    bool covered = false;
    int k = s & 7;
    if (k < KSUB) {
        int w = s >> 3;
        int id = idx[(b * WIN + w) * KSUB + k];
        covered = (id != 0) || (s == 0);
    }
    float4 v = make_float4(0.f, 0.f, 0.f, 0.f);
    if (!covered) v = reinterpret_cast<const float4*>(emb)[gid];
    reinterpret_cast<float4*>(out)[gid] = v;
}

// ---------------------------------------------------------------------------
// Kernel 3: TF32 GEMM (q,k for one head x 16 windows) + fused scores/softmax/
// contrib. grid = (256 window-tiles, 16 heads), 128 threads.
// ---------------------------------------------------------------------------
__global__ void __launch_bounds__(128)
gemm_scores_kernel(const float* __restrict__ Wt, const float* __restrict__ bias,
                   const int* __restrict__ idx) {
    extern __shared__ float sm[];
    float* sA = sm;                      // [96][36]
    float* sB = sm + 96 * SA_STRIDE;     // [128][36]
    float* sQK = sm;                     // [96][133]
    float* sAT = sm + 96 * SQK_STRIDE;   // [96][6] attn rows
    int* sMask = (int*)(sm + 96 * SQK_STRIDE + 96 * 6);  // [16]

    const int wt = blockIdx.x;
    const int h = blockIdx.y;
    const int tid = threadIdx.x;
    const int warp = tid >> 5;
    const int lane = tid & 31;
    const int g = lane >> 2;
    const int c = lane & 3;
    const int row0 = wt * MT;

    float acc[6][4][4];
#pragma unroll
    for (int m = 0; m < 6; m++)
#pragma unroll
        for (int n = 0; n < 4; n++)
#pragma unroll
            for (int e = 0; e < 4; e++) acc[m][n][e] = 0.f;

    for (int kk = 0; kk < HID; kk += KC) {
        // Stage A tile: 96 x 32 (768 float4 / 128 threads = 6 each)
#pragma unroll
        for (int it = 0; it < 6; it++) {
            int i = tid + it * 128;
            int r = i >> 3;
            int c4 = (i & 7) * 4;
            float4 v = *reinterpret_cast<const float4*>(
                g_X + (size_t)(row0 + r) * HID + kk + c4);
            float* dst = sA + r * SA_STRIDE + c4;
            dst[0] = to_tf32(v.x); dst[1] = to_tf32(v.y);
            dst[2] = to_tf32(v.z); dst[3] = to_tf32(v.w);
        }
        // Stage B tile: 128 x 32 (q rows then k rows of W)
#pragma unroll
        for (int it = 0; it < 8; it++) {
            int i = tid + it * 128;
            int r = i >> 3;
            int c4 = (i & 7) * 4;
            int wrow = (r < HD) ? (h * HD + r) : (HID + h * HD + (r - HD));
            float4 v = *reinterpret_cast<const float4*>(
                Wt + (size_t)wrow * HID + kk + c4);
            float* dst = sB + r * SB_STRIDE + c4;
            dst[0] = to_tf32(v.x); dst[1] = to_tf32(v.y);
            dst[2] = to_tf32(v.z); dst[3] = to_tf32(v.w);
        }
        __syncthreads();
#pragma unroll
        for (int ks = 0; ks < 4; ks++) {
            const int kb = ks * 8;
            uint32_t a[6][4];
#pragma unroll
            for (int m = 0; m < 6; m++) {
                a[m][0] = __float_as_uint(sA[(m * 16 + g) * SA_STRIDE + kb + c]);
                a[m][1] = __float_as_uint(sA[(m * 16 + g + 8) * SA_STRIDE + kb + c]);
                a[m][2] = __float_as_uint(sA[(m * 16 + g) * SA_STRIDE + kb + c + 4]);
                a[m][3] = __float_as_uint(sA[(m * 16 + g + 8) * SA_STRIDE + kb + c + 4]);
            }
#pragma unroll
            for (int n = 0; n < 4; n++) {
                int nb = warp * 32 + n * 8;
                uint32_t b0 = __float_as_uint(sB[(nb + g) * SB_STRIDE + kb + c]);
                uint32_t b1 = __float_as_uint(sB[(nb + g) * SB_STRIDE + kb + c + 4]);
#pragma unroll
                for (int m = 0; m < 6; m++)
                    mma_tf32(acc[m][n], a[m][0], a[m][1], a[m][2], a[m][3], b0, b1);
            }
        }
        __syncthreads();
    }

    // Epilogue: bias add, write q|k tile to smem (cols 0..63 = q, 64..127 = k)
#pragma unroll
    for (int m = 0; m < 6; m++)
#pragma unroll
        for (int n = 0; n < 4; n++) {
            int colbase = warp * 32 + n * 8 + c * 2;
#pragma unroll
            for (int e = 0; e < 4; e++) {
                int row = m * 16 + g + ((e >= 2) ? 8 : 0);
                int col = colbase + (e & 1);
                float bv = bias[(col < HD) ? (h * HD + col)
                                           : (HID + h * HD + (col - HD))];
                sQK[row * SQK_STRIDE + col] = acc[m][n][e] + bv;
            }
        }
    if (tid < WT_PER_BLK) {
        int bw = wt * WT_PER_BLK + tid;
        int mb = 0;
#pragma unroll
        for (int k2 = 0; k2 < KSUB; k2++) {
            int id = idx[bw * KSUB + k2];
            if (id != 0 || (((bw & (WIN - 1)) == 0) && k2 == 0)) mb |= (1 << k2);
        }
        sMask[tid] = mb;
    }
    __syncthreads();

    // scores (6x6 per window) + softmax rows
    if (tid < MT) {
        int w = tid / KSUB, i = tid - w * KSUB;
        int mbits = sMask[w];
        int mi = (mbits >> i) & 1;
        const float* qrow = sQK + (w * KSUB + i) * SQK_STRIDE;
        float sc[KSUB];
#pragma unroll
        for (int j = 0; j < KSUB; j++) {
            const float* krow = sQK + (w * KSUB + j) * SQK_STRIDE + HD;
            float d = 0.f;
#pragma unroll
            for (int x = 0; x < HD; x++) d += qrow[x] * krow[x];
            int mj = (mbits >> j) & 1;
            sc[j] = d * 0.125f + (float)(mi & mj);
        }
        float mx = sc[0];
#pragma unroll
        for (int j = 1; j < KSUB; j++) mx = fmaxf(mx, sc[j]);
        float ssum = 0.f;
#pragma unroll
        for (int j = 0; j < KSUB; j++) { sc[j] = expf(sc[j] - mx); ssum += sc[j]; }
        float inv = 1.f / ssum;
#pragma unroll
        for (int j = 0; j < KSUB; j++) sAT[tid * KSUB + j] = sc[j] * inv;
    }
    __syncthreads();

    // contrib partial for this head: sum_i pair_ij * attn_ij, * 1/NHEAD
    if (tid < MT) {
        int w = tid / KSUB, j = tid - w * KSUB;
        int mbits = sMask[w];
        float cv = 0.f;
        if ((mbits >> j) & 1) {
#pragma unroll
            for (int i2 = 0; i2 < KSUB; i2++)
                if ((mbits >> i2) & 1) cv += sAT[(w * KSUB + i2) * KSUB + j];
        }
        g_contribH[h * NROWS + (wt * WT_PER_BLK + w) * KSUB + j] =
            cv * (1.0f / (float)NHEAD);
    }
}

// ---------------------------------------------------------------------------
// Kernel 4: finalize — sum contrib over heads, normalize, weighted gather-sum,
// scatter unified row to out[b, 8w]. One block per window.
// ---------------------------------------------------------------------------
__global__ void __launch_bounds__(256)
finalize_kernel(float* __restrict__ out) {
    int bw = blockIdx.x;
    __shared__ float scon[KSUB];
    if (threadIdx.x < KSUB) {
        float s = 0.f;
        int base = bw * KSUB + threadIdx.x;
#pragma unroll
        for (int h = 0; h < NHEAD; h++) s += g_contribH[h * NROWS + base];
        scon[threadIdx.x] = s;
    }
    __syncthreads();
    float sum = scon[0] + scon[1] + scon[2] + scon[3] + scon[4] + scon[5];
    float inv = 1.0f / (sum + 1e-8f);
    int t = threadIdx.x;  // 256 float4 columns
    const float4* gx = reinterpret_cast<const float4*>(g_X + (size_t)bw * KSUB * HID);
    float4 u = make_float4(0.f, 0.f, 0.f, 0.f);
#pragma unroll
    for (int k = 0; k < KSUB; k++) {
        float cw = scon[k] * inv;
        float4 v = gx[k * (HID / 4) + t];
        u.x += cw * v.x; u.y += cw * v.y; u.z += cw * v.z; u.w += cw * v.w;
    }
    int b = bw >> 7, w = bw & (WIN - 1);
    reinterpret_cast<float4*>(out)[(size_t)(b * SEQ + w * 8) * (HID / 4) + t] = u;
}

// ---------------------------------------------------------------------------
extern "C" void kernel_launch(void* const* d_in, const int* in_sizes, int n_in,
                              void* d_out, int out_size) {
    const float* emb  = (const float*)d_in[0];   // (32,1024,1024) f32
    const float* Wt   = (const float*)d_in[1];   // (3072,1024) f32
    const float* bias = (const float*)d_in[2];   // (3072,) f32
    const int* idx    = (const int*)d_in[3];     // (32,128,6) i32
    float* out = (float*)d_out;
    (void)in_sizes; (void)n_in; (void)out_size;

    cudaFuncSetAttribute(gemm_scores_kernel,
                         cudaFuncAttributeMaxDynamicSharedMemorySize, SMEM_BYTES);

    gather_kernel<<<NROWS, 256>>>(emb, idx);
    passthrough_kernel<<<(BATCH * SEQ * HID / 4) / 256, 256>>>(emb, idx, out);
    gemm_scores_kernel<<<dim3(NWIN / WT_PER_BLK, NHEAD), 128, SMEM_BYTES>>>(Wt, bias, idx);
    finalize_kernel<<<NWIN, 256>>>(out);
}

// round 3
// speedup vs baseline: 1.9283x; 1.9283x over previous
#include <cuda_runtime.h>
#include <cuda_bf16.h>
#include <cstdint>

// Problem constants
#define BATCH 32
#define SEQ   1024
#define HID   1024
#define WIN   128
#define KSUB  6
#define NHEAD 16
#define HD    64
#define NWIN  (BATCH * WIN)        // 4096
#define NROWS (NWIN * KSUB)        // 24576

// GEMM tiling: 16 windows (M=96) x 2 heads (N=256), 256 threads (8 warps 2x4)
#define WPB 16
#define HPB 2
#define MT (WPB * KSUB)            // 96
#define NT (HPB * 128)             // 256
#define KC 32                      // k per stage
#define STAGES 4
#define NKITER (HID / KC)          // 32

#define ASTR 40                    // bf16 elems per A row in smem (32 + 8 pad)
#define BSTR 40
#define A_ELEMS (MT * ASTR)        // 3840
#define B_ELEMS (NT * BSTR)        // 10240
#define STAGE_ELEMS (A_ELEMS + B_ELEMS)       // 14080 bf16
#define STAGE_BYTES (STAGE_ELEMS * 2)         // 28160
#define SMEM_BYTES  (STAGE_BYTES * STAGES)    // 112640

// Epilogue region (unioned over stage buffers)
#define SQ 260                     // fp32 stride for QK rows (256 + 4 pad)

__device__ __nv_bfloat16 g_Xb[(size_t)NROWS * HID];   // gathered masked rows, bf16
__device__ __nv_bfloat16 g_Wb[(size_t)2048 * HID];    // permuted [head][q64|k64][1024]
__device__ float g_contribH[(NHEAD / HPB) * NROWS];   // per-block-row contrib partials

__device__ __forceinline__ void cp16(uint32_t dst, const void* src) {
    asm volatile("cp.async.cg.shared.global [%0], [%1], 16;\n" :: "r"(dst), "l"(src));
}
__device__ __forceinline__ void cp_commit() {
    asm volatile("cp.async.commit_group;\n" ::: "memory");
}

__device__ __forceinline__ void mma_bf16(float c[4], uint32_t a0, uint32_t a1,
                                         uint32_t a2, uint32_t a3,
                                         uint32_t b0, uint32_t b1) {
    asm volatile(
        "mma.sync.aligned.m16n8k16.row.col.f32.bf16.bf16.f32 "
        "{%0,%1,%2,%3}, {%4,%5,%6,%7}, {%8,%9}, {%0,%1,%2,%3};\n"
        : "+f"(c[0]), "+f"(c[1]), "+f"(c[2]), "+f"(c[3])
        : "r"(a0), "r"(a1), "r"(a2), "r"(a3), "r"(b0), "r"(b1));
}

// ---------------------------------------------------------------------------
// Gather masked subtoken rows -> bf16. One block per row, 256 threads.
// valid(bw,k) = idx!=0 || (w==0 && k==0)
// ---------------------------------------------------------------------------
__global__ void __launch_bounds__(256)
gather_bf16_kernel(const float* __restrict__ emb, const int* __restrict__ idx) {
    int row = blockIdx.x;
    int t = threadIdx.x;              // handles cols 4t..4t+3
    int bw = row / KSUB;
    int k = row - bw * KSUB;
    int id = idx[row];
    bool valid = (id != 0) || (((bw & (WIN - 1)) == 0) && (k == 0));
    int b = bw >> 7;
    float4 v = make_float4(0.f, 0.f, 0.f, 0.f);
    if (valid)
        v = reinterpret_cast<const float4*>(emb)[(size_t)(b * SEQ + id) * 256 + t];
    __nv_bfloat162 lo = __floats2bfloat162_rn(v.x, v.y);
    __nv_bfloat162 hi = __floats2bfloat162_rn(v.z, v.w);
    uint2 pk;
    pk.x = *reinterpret_cast<uint32_t*>(&lo);
    pk.y = *reinterpret_cast<uint32_t*>(&hi);
    reinterpret_cast<uint2*>(g_Xb)[(size_t)row * 256 + t] = pk;
}

// ---------------------------------------------------------------------------
// Convert & permute W[:2048] -> g_Wb, row order [head][q(64)|k(64)].
// One block per output row.
// ---------------------------------------------------------------------------
__global__ void __launch_bounds__(256)
prep_w_kernel(const float* __restrict__ Wt) {
    int o = blockIdx.x;               // 0..2047
    int t = threadIdx.x;
    int h = o >> 7;
    int r = o & 127;
    int src = ((r >= 64) ? HID : 0) + h * HD + (r & 63);
    float4 v = reinterpret_cast<const float4*>(Wt)[(size_t)src * 256 + t];
    __nv_bfloat162 lo = __floats2bfloat162_rn(v.x, v.y);
    __nv_bfloat162 hi = __floats2bfloat162_rn(v.z, v.w);
    uint2 pk;
    pk.x = *reinterpret_cast<uint32_t*>(&lo);
    pk.y = *reinterpret_cast<uint32_t*>(&hi);
    reinterpret_cast<uint2*>(g_Wb)[(size_t)o * 256 + t] = pk;
}

// ---------------------------------------------------------------------------
// Passthrough with zeroing of covered positions.
// ---------------------------------------------------------------------------
__global__ void __launch_bounds__(256)
passthrough_kernel(const float* __restrict__ emb, const int* __restrict__ idx,
                   float* __restrict__ out) {
    int gid = blockIdx.x * 256 + threadIdx.x;
    int sg = gid >> 8;
    int b = sg >> 10;
    int s = sg & (SEQ - 1);
    bool covered = false;
    int k = s & 7;
    if (k < KSUB) {
        int w = s >> 3;
        int id = idx[(b * WIN + w) * KSUB + k];
        covered = (id != 0) || (s == 0);
    }
    float4 v = make_float4(0.f, 0.f, 0.f, 0.f);
    if (!covered) v = reinterpret_cast<const float4*>(emb)[gid];
    reinterpret_cast<float4*>(out)[gid] = v;
}

// ---------------------------------------------------------------------------
// bf16 GEMM (q,k for 2 heads x 16 windows) + fused scores/softmax/contrib.
// grid = (256, 8), 256 threads.
// ---------------------------------------------------------------------------
__global__ void __launch_bounds__(256)
gemm_scores_kernel(const float* __restrict__ bias, const int* __restrict__ idx) {
    extern __shared__ char smem_raw[];
    __nv_bfloat16* smem = reinterpret_cast<__nv_bfloat16*>(smem_raw);
    float* sQK = reinterpret_cast<float*>(smem_raw);        // [96][SQ]
    float* sAT = sQK + MT * SQ;                             // [2][96][6]
    int* sMask = reinterpret_cast<int*>(sAT + 2 * MT * KSUB);  // [16]

    const int wt = blockIdx.x;
    const int by = blockIdx.y;        // head pair
    const int tid = threadIdx.x;
    const int warp = tid >> 5;
    const int lane = tid & 31;
    const int g = lane >> 2;
    const int c = lane & 3;
    const int mw = warp >> 2;         // 0..1
    const int nw = warp & 3;          // 0..3
    const int row0 = wt * MT;
    const int wrow0 = by * NT;        // g_Wb base row

    const uint32_t smem_u32 = (uint32_t)__cvta_generic_to_shared(smem_raw);

    float acc[3][8][4];
#pragma unroll
    for (int m = 0; m < 3; m++)
#pragma unroll
        for (int n = 0; n < 8; n++)
#pragma unroll
            for (int e = 0; e < 4; e++) acc[m][n][e] = 0.f;

    // ---- async stage issue ----
    auto issue = [&](int s, int kk) {
        uint32_t base = smem_u32 + (s & (STAGES - 1)) * STAGE_BYTES;
        const __nv_bfloat16* asrc = g_Xb + (size_t)row0 * HID + kk;
        // A: 96 rows x 64B = 384 chunks
        {
            int cA = tid;
            cp16(base + (cA >> 2) * (ASTR * 2) + (cA & 3) * 16,
                 asrc + (size_t)(cA >> 2) * HID + (cA & 3) * 8);
            if (tid < 128) {
                int c2 = tid + 256;
                cp16(base + (c2 >> 2) * (ASTR * 2) + (c2 & 3) * 16,
                     asrc + (size_t)(c2 >> 2) * HID + (c2 & 3) * 8);
            }
        }
        // B: 256 rows x 64B = 1024 chunks
        const __nv_bfloat16* bsrc = g_Wb + (size_t)wrow0 * HID + kk;
        uint32_t bbase = base + A_ELEMS * 2;
#pragma unroll
        for (int i = 0; i < 4; i++) {
            int cB = tid + i * 256;
            cp16(bbase + (cB >> 2) * (BSTR * 2) + (cB & 3) * 16,
                 bsrc + (size_t)(cB >> 2) * HID + (cB & 3) * 8);
        }
    };

    // prologue: stages 0..2
    issue(0, 0); cp_commit();
    issue(1, KC); cp_commit();
    issue(2, 2 * KC); cp_commit();

    for (int it = 0; it < NKITER; ++it) {
        asm volatile("cp.async.wait_group 2;\n" ::: "memory");
        __syncthreads();
        if (it + 3 < NKITER) issue(it + 3, (it + 3) * KC);
        cp_commit();

        const __nv_bfloat16* stage = smem + (it & (STAGES - 1)) * STAGE_ELEMS;
        const __nv_bfloat16* sa = stage + mw * 48 * ASTR;
        const __nv_bfloat16* sb = stage + A_ELEMS + nw * 64 * BSTR;
#pragma unroll
        for (int ks = 0; ks < 2; ks++) {
            const int kb = ks * 16;
            uint32_t a[3][4];
#pragma unroll
            for (int m = 0; m < 3; m++) {
                const __nv_bfloat16* ap = sa + (m * 16 + g) * ASTR + kb + c * 2;
                a[m][0] = *reinterpret_cast<const uint32_t*>(ap);
                a[m][1] = *reinterpret_cast<const uint32_t*>(ap + 8 * ASTR);
                a[m][2] = *reinterpret_cast<const uint32_t*>(ap + 8);
                a[m][3] = *reinterpret_cast<const uint32_t*>(ap + 8 * ASTR + 8);
            }
#pragma unroll
            for (int n = 0; n < 8; n++) {
                const __nv_bfloat16* bp = sb + (n * 8 + g) * BSTR + kb + c * 2;
                uint32_t b0 = *reinterpret_cast<const uint32_t*>(bp);
                uint32_t b1 = *reinterpret_cast<const uint32_t*>(bp + 8);
#pragma unroll
                for (int m = 0; m < 3; m++)
                    mma_bf16(acc[m][n], a[m][0], a[m][1], a[m][2], a[m][3], b0, b1);
            }
        }
    }
    asm volatile("cp.async.wait_group 0;\n" ::: "memory");
    __syncthreads();   // stage buffers dead; sQK region now writable

    // ---- epilogue: write QK tile (bias add) ----
    const int hh = nw >> 1;           // head within pair
    const int qk = nw & 1;            // 0 = q, 1 = k
#pragma unroll
    for (int m = 0; m < 3; m++)
#pragma unroll
        for (int n = 0; n < 8; n++)
#pragma unroll
            for (int e = 0; e < 4; e++) {
                int row = mw * 48 + m * 16 + g + ((e >= 2) ? 8 : 0);
                int loc = n * 8 + c * 2 + (e & 1);
                int col = hh * 128 + qk * 64 + loc;
                int bidx = (qk ? HID : 0) + (2 * by + hh) * HD + loc;
                sQK[row * SQ + col] = acc[m][n][e] + bias[bidx];
            }
    if (tid < WPB) {
        int bw = wt * WPB + tid;
        int mb = 0;
#pragma unroll
        for (int k2 = 0; k2 < KSUB; k2++) {
            int id = idx[bw * KSUB + k2];
            if (id != 0 || (((bw & (WIN - 1)) == 0) && k2 == 0)) mb |= (1 << k2);
        }
        sMask[tid] = mb;
    }
    __syncthreads();

    // ---- scores + softmax: 192 rows (2 heads x 96) ----
    if (tid < 2 * MT) {
        int h2 = tid / MT;
        int r = tid - h2 * MT;
        int w = r / KSUB, i = r - w * KSUB;
        int mbits = sMask[w];
        int mi = (mbits >> i) & 1;
        const float* qrow = sQK + (w * KSUB + i) * SQ + h2 * 128;
        float sc[KSUB];
#pragma unroll
        for (int j = 0; j < KSUB; j++) {
            const float* krow = sQK + (w * KSUB + j) * SQ + h2 * 128 + HD;
            float d = 0.f;
#pragma unroll
            for (int x = 0; x < HD; x++) d += qrow[x] * krow[x];
            int mj = (mbits >> j) & 1;
            sc[j] = d * 0.125f + (float)(mi & mj);
        }
        float mx = sc[0];
#pragma unroll
        for (int j = 1; j < KSUB; j++) mx = fmaxf(mx, sc[j]);
        float ssum = 0.f;
#pragma unroll
        for (int j = 0; j < KSUB; j++) { sc[j] = expf(sc[j] - mx); ssum += sc[j]; }
        float inv = 1.f / ssum;
#pragma unroll
        for (int j = 0; j < KSUB; j++) sAT[(h2 * MT + r) * KSUB + j] = sc[j] * inv;
    }
    __syncthreads();

    // ---- contrib partial (both heads summed), * 1/NHEAD ----
    if (tid < MT) {
        int w = tid / KSUB, j = tid - w * KSUB;
        int mbits = sMask[w];
        float cv = 0.f;
        if ((mbits >> j) & 1) {
#pragma unroll
            for (int h2 = 0; h2 < 2; h2++)
#pragma unroll
                for (int i2 = 0; i2 < KSUB; i2++)
                    if ((mbits >> i2) & 1)
                        cv += sAT[(h2 * MT + w * KSUB + i2) * KSUB + j];
        }
        g_contribH[(size_t)by * NROWS + (wt * WPB + w) * KSUB + j] =
            cv * (1.0f / (float)NHEAD);
    }
}

// ---------------------------------------------------------------------------
// Finalize: sum contrib over head-pairs, normalize, fp32 gather-weighted sum.
// ---------------------------------------------------------------------------
__global__ void __launch_bounds__(256)
finalize_kernel(const float* __restrict__ emb, const int* __restrict__ idx,
                float* __restrict__ out) {
    int bw = blockIdx.x;
    __shared__ float scon[KSUB];
    __shared__ int sid[KSUB];
    if (threadIdx.x < KSUB) {
        float s = 0.f;
        int base = bw * KSUB + threadIdx.x;
#pragma unroll
        for (int by = 0; by < NHEAD / HPB; by++) s += g_contribH[(size_t)by * NROWS + base];
        scon[threadIdx.x] = s;
        sid[threadIdx.x] = idx[base];
    }
    __syncthreads();
    float sum = scon[0] + scon[1] + scon[2] + scon[3] + scon[4] + scon[5];
    float inv = 1.0f / (sum + 1e-8f);
    int t = threadIdx.x;
    int b = bw >> 7;
    float4 u = make_float4(0.f, 0.f, 0.f, 0.f);
#pragma unroll
    for (int k = 0; k < KSUB; k++) {
        float cw = scon[k] * inv;   // exactly 0 for invalid k
        float4 v = reinterpret_cast<const float4*>(emb)[(size_t)(b * SEQ + sid[k]) * 256 + t];
        u.x += cw * v.x; u.y += cw * v.y; u.z += cw * v.z; u.w += cw * v.w;
    }
    int w = bw & (WIN - 1);
    reinterpret_cast<float4*>(out)[(size_t)(b * SEQ + w * 8) * 256 + t] = u;
}

// ---------------------------------------------------------------------------
extern "C" void kernel_launch(void* const* d_in, const int* in_sizes, int n_in,
                              void* d_out, int out_size) {
    const float* emb  = (const float*)d_in[0];
    const float* Wt   = (const float*)d_in[1];
    const float* bias = (const float*)d_in[2];
    const int* idx    = (const int*)d_in[3];
    float* out = (float*)d_out;
    (void)in_sizes; (void)n_in; (void)out_size;

    cudaFuncSetAttribute(gemm_scores_kernel,
                         cudaFuncAttributeMaxDynamicSharedMemorySize, SMEM_BYTES);

    prep_w_kernel<<<2048, 256>>>(Wt);
    gather_bf16_kernel<<<NROWS, 256>>>(emb, idx);
    passthrough_kernel<<<(BATCH * SEQ * HID / 4) / 256, 256>>>(emb, idx, out);
    gemm_scores_kernel<<<dim3(NWIN / WPB, NHEAD / HPB), 256, SMEM_BYTES>>>(bias, idx);
    finalize_kernel<<<NWIN, 256>>>(emb, idx, out);
}

// round 4
// speedup vs baseline: 2.0453x; 1.0607x over previous
#include <cuda_runtime.h>
#include <cuda_bf16.h>
#include <cstdint>

// Problem constants
#define BATCH 32
#define SEQ   1024
#define HID   1024
#define WIN   128
#define KSUB  6
#define NHEAD 16
#define HD    64
#define NWIN  (BATCH * WIN)        // 4096
#define NROWS (NWIN * KSUB)        // 24576

// GEMM tiling: 16 windows (M=96) x 2 heads (N=256), 256 threads (8 warps 2x4)
#define WPB 16
#define HPB 2
#define MT (WPB * KSUB)            // 96
#define NT (HPB * 128)             // 256
#define KC 32                      // k per stage
#define STAGES 3
#define NKITER (HID / KC)          // 32

#define ASTR 40                    // bf16 elems per A row in smem (32 + 8 pad)
#define BSTR 40
#define A_ELEMS (MT * ASTR)        // 3840
#define B_ELEMS (NT * BSTR)        // 10240
#define STAGE_ELEMS (A_ELEMS + B_ELEMS)       // 14080 bf16
#define STAGE_BYTES (STAGE_ELEMS * 2)         // 28160
#define SMEM_BYTES  (STAGE_BYTES * STAGES)    // 84480

// Epilogue region (unioned over stage buffers): bf16 QK tile
#define SQH 264                    // bf16 stride (256 + 8 pad)

__device__ __nv_bfloat16 g_Xb[(size_t)NROWS * HID];   // gathered masked rows, bf16
__device__ __nv_bfloat16 g_Wb[(size_t)2048 * HID];    // permuted [head][q64|k64][1024]
__device__ float g_contribH[(NHEAD / HPB) * NROWS];   // per-block-row contrib partials

__device__ __forceinline__ void cp16(uint32_t dst, const void* src) {
    asm volatile("cp.async.cg.shared.global [%0], [%1], 16;\n" :: "r"(dst), "l"(src));
}
__device__ __forceinline__ void cp_commit() {
    asm volatile("cp.async.commit_group;\n" ::: "memory");
}
__device__ __forceinline__ void ldsm_x4(uint32_t r[4], uint32_t addr) {
    asm volatile("ldmatrix.sync.aligned.m8n8.x4.shared.b16 {%0,%1,%2,%3}, [%4];"
                 : "=r"(r[0]), "=r"(r[1]), "=r"(r[2]), "=r"(r[3]) : "r"(addr));
}

__device__ __forceinline__ void mma_bf16(float c[4], uint32_t a0, uint32_t a1,
                                         uint32_t a2, uint32_t a3,
                                         uint32_t b0, uint32_t b1) {
    asm volatile(
        "mma.sync.aligned.m16n8k16.row.col.f32.bf16.bf16.f32 "
        "{%0,%1,%2,%3}, {%4,%5,%6,%7}, {%8,%9}, {%0,%1,%2,%3};\n"
        : "+f"(c[0]), "+f"(c[1]), "+f"(c[2]), "+f"(c[3])
        : "r"(a0), "r"(a1), "r"(a2), "r"(a3), "r"(b0), "r"(b1));
}

// ---------------------------------------------------------------------------
// Gather masked subtoken rows -> bf16. One block per row, 256 threads.
// valid(bw,k) = idx!=0 || (w==0 && k==0)
// ---------------------------------------------------------------------------
__global__ void __launch_bounds__(256)
gather_bf16_kernel(const float* __restrict__ emb, const int* __restrict__ idx) {
    int row = blockIdx.x;
    int t = threadIdx.x;
    int bw = row / KSUB;
    int k = row - bw * KSUB;
    int id = idx[row];
    bool valid = (id != 0) || (((bw & (WIN - 1)) == 0) && (k == 0));
    int b = bw >> 7;
    float4 v = make_float4(0.f, 0.f, 0.f, 0.f);
    if (valid)
        v = reinterpret_cast<const float4*>(emb)[(size_t)(b * SEQ + id) * 256 + t];
    __nv_bfloat162 lo = __floats2bfloat162_rn(v.x, v.y);
    __nv_bfloat162 hi = __floats2bfloat162_rn(v.z, v.w);
    uint2 pk;
    pk.x = *reinterpret_cast<uint32_t*>(&lo);
    pk.y = *reinterpret_cast<uint32_t*>(&hi);
    reinterpret_cast<uint2*>(g_Xb)[(size_t)row * 256 + t] = pk;
}

// ---------------------------------------------------------------------------
// Convert & permute W[:2048] -> g_Wb, row order [head][q(64)|k(64)].
// ---------------------------------------------------------------------------
__global__ void __launch_bounds__(256)
prep_w_kernel(const float* __restrict__ Wt) {
    int o = blockIdx.x;
    int t = threadIdx.x;
    int h = o >> 7;
    int r = o & 127;
    int src = ((r >= 64) ? HID : 0) + h * HD + (r & 63);
    float4 v = reinterpret_cast<const float4*>(Wt)[(size_t)src * 256 + t];
    __nv_bfloat162 lo = __floats2bfloat162_rn(v.x, v.y);
    __nv_bfloat162 hi = __floats2bfloat162_rn(v.z, v.w);
    uint2 pk;
    pk.x = *reinterpret_cast<uint32_t*>(&lo);
    pk.y = *reinterpret_cast<uint32_t*>(&hi);
    reinterpret_cast<uint2*>(g_Wb)[(size_t)o * 256 + t] = pk;
}

// ---------------------------------------------------------------------------
// Passthrough with zeroing of covered positions.
// ---------------------------------------------------------------------------
__global__ void __launch_bounds__(256)
passthrough_kernel(const float* __restrict__ emb, const int* __restrict__ idx,
                   float* __restrict__ out) {
    int gid = blockIdx.x * 256 + threadIdx.x;
    int sg = gid >> 8;
    int b = sg >> 10;
    int s = sg & (SEQ - 1);
    bool covered = false;
    int k = s & 7;
    if (k < KSUB) {
        int w = s >> 3;
        int id = idx[(b * WIN + w) * KSUB + k];
        covered = (id != 0) || (s == 0);
    }
    float4 v = make_float4(0.f, 0.f, 0.f, 0.f);
    if (!covered) v = reinterpret_cast<const float4*>(emb)[gid];
    reinterpret_cast<float4*>(out)[gid] = v;
}

// ---------------------------------------------------------------------------
// bf16 GEMM (q,k for 2 heads x 16 windows) + fused scores/softmax/contrib.
// grid = (256, 8), 256 threads, 2 blocks/SM.
// ---------------------------------------------------------------------------
__global__ void __launch_bounds__(256, 2)
gemm_scores_kernel(const float* __restrict__ bias, const int* __restrict__ idx) {
    extern __shared__ char smem_raw[];
    __nv_bfloat16* sQKh = reinterpret_cast<__nv_bfloat16*>(smem_raw); // [96][SQH]
    float* sAT = reinterpret_cast<float*>(smem_raw + MT * SQH * 2);   // [2][96][6]
    int* sMask = reinterpret_cast<int*>(sAT + 2 * MT * KSUB);         // [16]

    const int wt = blockIdx.x;
    const int by = blockIdx.y;        // head pair
    const int tid = threadIdx.x;
    const int warp = tid >> 5;
    const int lane = tid & 31;
    const int g = lane >> 2;
    const int c = lane & 3;
    const int mw = warp >> 2;         // 0..1
    const int nw = warp & 3;          // 0..3
    const int row0 = wt * MT;
    const int wrow0 = by * NT;

    const uint32_t smem_u32 = (uint32_t)__cvta_generic_to_shared(smem_raw);

    // ldmatrix lane offsets (bytes within a stage)
    const int arow = mw * 48 + ((lane >> 3) & 1) * 8 + (lane & 7);
    const int acol = (lane >> 4) * 8;
    const uint32_t a_off = (uint32_t)(arow * ASTR + acol) * 2;
    const int brow = nw * 64 + ((lane >> 4) & 1) * 8 + (lane & 7);
    const int bcol = ((lane >> 3) & 1) * 8;
    const uint32_t b_off = (uint32_t)A_ELEMS * 2 + (uint32_t)(brow * BSTR + bcol) * 2;

    float acc[3][8][4];
#pragma unroll
    for (int m = 0; m < 3; m++)
#pragma unroll
        for (int n = 0; n < 8; n++)
#pragma unroll
            for (int e = 0; e < 4; e++) acc[m][n][e] = 0.f;

    auto issue = [&](int s, int kk) {
        uint32_t base = smem_u32 + (uint32_t)(s % STAGES) * STAGE_BYTES;
        const __nv_bfloat16* asrc = g_Xb + (size_t)row0 * HID + kk;
        {
            int cA = tid;
            cp16(base + (cA >> 2) * (ASTR * 2) + (cA & 3) * 16,
                 asrc + (size_t)(cA >> 2) * HID + (cA & 3) * 8);
            if (tid < 128) {
                int c2 = tid + 256;
                cp16(base + (c2 >> 2) * (ASTR * 2) + (c2 & 3) * 16,
                     asrc + (size_t)(c2 >> 2) * HID + (c2 & 3) * 8);
            }
        }
        const __nv_bfloat16* bsrc = g_Wb + (size_t)wrow0 * HID + kk;
        uint32_t bbase = base + A_ELEMS * 2;
#pragma unroll
        for (int i = 0; i < 4; i++) {
            int cB = tid + i * 256;
            cp16(bbase + (cB >> 2) * (BSTR * 2) + (cB & 3) * 16,
                 bsrc + (size_t)(cB >> 2) * HID + (cB & 3) * 8);
        }
    };

    issue(0, 0); cp_commit();
    issue(1, KC); cp_commit();

    for (int it = 0; it < NKITER; ++it) {
        asm volatile("cp.async.wait_group 1;\n" ::: "memory");
        __syncthreads();
        if (it + 2 < NKITER) issue(it + 2, (it + 2) * KC);
        cp_commit();

        uint32_t stage_base = smem_u32 + (uint32_t)(it % STAGES) * STAGE_BYTES;
#pragma unroll
        for (int ks = 0; ks < 2; ks++) {
            const int kb = ks * 16;
            uint32_t a[3][4];
#pragma unroll
            for (int m = 0; m < 3; m++)
                ldsm_x4(a[m], stage_base + a_off + (uint32_t)(m * 16 * ASTR + kb) * 2);
#pragma unroll
            for (int np = 0; np < 4; np++) {
                uint32_t b[4];
                ldsm_x4(b, stage_base + b_off + (uint32_t)(np * 16 * BSTR + kb) * 2);
#pragma unroll
                for (int m = 0; m < 3; m++) {
                    mma_bf16(acc[m][np * 2 + 0], a[m][0], a[m][1], a[m][2], a[m][3],
                             b[0], b[1]);
                    mma_bf16(acc[m][np * 2 + 1], a[m][0], a[m][1], a[m][2], a[m][3],
                             b[2], b[3]);
                }
            }
        }
    }
    asm volatile("cp.async.wait_group 0;\n" ::: "memory");
    __syncthreads();   // stage buffers dead; epilogue region writable

    // ---- epilogue: write QK tile (bias add, bf16) ----
    const int hh = nw >> 1;
    const int qk = nw & 1;
#pragma unroll
    for (int m = 0; m < 3; m++)
#pragma unroll
        for (int n = 0; n < 8; n++) {
            int row = mw * 48 + m * 16 + g;
            int loc = n * 8 + c * 2;
            int col = hh * 128 + qk * 64 + loc;
            int bidx = (qk ? HID : 0) + (2 * by + hh) * HD + loc;
            float b0v = bias[bidx], b1v = bias[bidx + 1];
            *reinterpret_cast<__nv_bfloat162*>(sQKh + row * SQH + col) =
                __floats2bfloat162_rn(acc[m][n][0] + b0v, acc[m][n][1] + b1v);
            *reinterpret_cast<__nv_bfloat162*>(sQKh + (row + 8) * SQH + col) =
                __floats2bfloat162_rn(acc[m][n][2] + b0v, acc[m][n][3] + b1v);
        }
    if (tid < WPB) {
        int bw = wt * WPB + tid;
        int mb = 0;
#pragma unroll
        for (int k2 = 0; k2 < KSUB; k2++) {
            int id = idx[bw * KSUB + k2];
            if (id != 0 || (((bw & (WIN - 1)) == 0) && k2 == 0)) mb |= (1 << k2);
        }
        sMask[tid] = mb;
    }
    __syncthreads();

    // ---- scores + softmax: 192 rows (2 heads x 96) ----
    if (tid < 2 * MT) {
        int h2 = tid / MT;
        int r = tid - h2 * MT;
        int w = r / KSUB, i = r - w * KSUB;
        int mbits = sMask[w];
        int mi = (mbits >> i) & 1;
        const __nv_bfloat162* qrow = reinterpret_cast<const __nv_bfloat162*>(
            sQKh + (w * KSUB + i) * SQH + h2 * 128);
        float sc[KSUB];
#pragma unroll
        for (int j = 0; j < KSUB; j++) {
            const __nv_bfloat162* krow = reinterpret_cast<const __nv_bfloat162*>(
                sQKh + (w * KSUB + j) * SQH + h2 * 128 + HD);
            float d = 0.f;
#pragma unroll
            for (int x = 0; x < HD / 2; x++) {
                float2 qv = __bfloat1622float2(qrow[x]);
                float2 kv = __bfloat1622float2(krow[x]);
                d += qv.x * kv.x + qv.y * kv.y;
            }
            int mj = (mbits >> j) & 1;
            sc[j] = d * 0.125f + (float)(mi & mj);
        }
        float mx = sc[0];
#pragma unroll
        for (int j = 1; j < KSUB; j++) mx = fmaxf(mx, sc[j]);
        float ssum = 0.f;
#pragma unroll
        for (int j = 0; j < KSUB; j++) { sc[j] = expf(sc[j] - mx); ssum += sc[j]; }
        float inv = 1.f / ssum;
#pragma unroll
        for (int j = 0; j < KSUB; j++) sAT[(h2 * MT + r) * KSUB + j] = sc[j] * inv;
    }
    __syncthreads();

    // ---- contrib partial (both heads summed), * 1/NHEAD ----
    if (tid < MT) {
        int w = tid / KSUB, j = tid - w * KSUB;
        int mbits = sMask[w];
        float cv = 0.f;
        if ((mbits >> j) & 1) {
#pragma unroll
            for (int h2 = 0; h2 < 2; h2++)
#pragma unroll
                for (int i2 = 0; i2 < KSUB; i2++)
                    if ((mbits >> i2) & 1)
                        cv += sAT[(h2 * MT + w * KSUB + i2) * KSUB + j];
        }
        g_contribH[(size_t)by * NROWS + (wt * WPB + w) * KSUB + j] =
            cv * (1.0f / (float)NHEAD);
    }
}

// ---------------------------------------------------------------------------
// Finalize: sum contrib over head-pairs, normalize, fp32 gather-weighted sum.
// ---------------------------------------------------------------------------
__global__ void __launch_bounds__(256)
finalize_kernel(const float* __restrict__ emb, const int* __restrict__ idx,
                float* __restrict__ out) {
    int bw = blockIdx.x;
    __shared__ float scon[KSUB];
    __shared__ int sid[KSUB];
    if (threadIdx.x < KSUB) {
        float s = 0.f;
        int base = bw * KSUB + threadIdx.x;
#pragma unroll
        for (int by = 0; by < NHEAD / HPB; by++) s += g_contribH[(size_t)by * NROWS + base];
        scon[threadIdx.x] = s;
        sid[threadIdx.x] = idx[base];
    }
    __syncthreads();
    float sum = scon[0] + scon[1] + scon[2] + scon[3] + scon[4] + scon[5];
    float inv = 1.0f / (sum + 1e-8f);
    int t = threadIdx.x;
    int b = bw >> 7;
    float4 u = make_float4(0.f, 0.f, 0.f, 0.f);
#pragma unroll
    for (int k = 0; k < KSUB; k++) {
        float cw = scon[k] * inv;
        float4 v = reinterpret_cast<const float4*>(emb)[(size_t)(b * SEQ + sid[k]) * 256 + t];
        u.x += cw * v.x; u.y += cw * v.y; u.z += cw * v.z; u.w += cw * v.w;
    }
    int w = bw & (WIN - 1);
    reinterpret_cast<float4*>(out)[(size_t)(b * SEQ + w * 8) * 256 + t] = u;
}

// ---------------------------------------------------------------------------
extern "C" void kernel_launch(void* const* d_in, const int* in_sizes, int n_in,
                              void* d_out, int out_size) {
    const float* emb  = (const float*)d_in[0];
    const float* Wt   = (const float*)d_in[1];
    const float* bias = (const float*)d_in[2];
    const int* idx    = (const int*)d_in[3];
    float* out = (float*)d_out;
    (void)in_sizes; (void)n_in; (void)out_size;

    cudaFuncSetAttribute(gemm_scores_kernel,
                         cudaFuncAttributeMaxDynamicSharedMemorySize, SMEM_BYTES);

    prep_w_kernel<<<2048, 256>>>(Wt);
    gather_bf16_kernel<<<NROWS, 256>>>(emb, idx);
    passthrough_kernel<<<(BATCH * SEQ * HID / 4) / 256, 256>>>(emb, idx, out);
    gemm_scores_kernel<<<dim3(NWIN / WPB, NHEAD / HPB), 256, SMEM_BYTES>>>(bias, idx);
    finalize_kernel<<<NWIN, 256>>>(emb, idx, out);
}

// round 10
// speedup vs baseline: 2.6897x; 1.3151x over previous
#include <cuda_runtime.h>
#include <cuda_bf16.h>
#include <cstdint>

// Problem constants
#define BATCH 32
#define SEQ   1024
#define HID   1024
#define WIN   128
#define KSUB  6
#define NHEAD 16
#define HD    64
#define NWIN  (BATCH * WIN)        // 4096
#define NROWS (NWIN * KSUB)        // 24576

// GEMM tiling: 96 compacted rows (variable #windows) x 2 heads (N=256)
#define HPB 2
#define MT 96
#define NT (HPB * 128)
#define KC 32
#define STAGES 3
#define NKITER (HID / KC)          // 32
#define MAXTILES 264

#define ASTR 40
#define BSTR 40
#define A_ELEMS (MT * ASTR)        // 3840
#define B_ELEMS (NT * BSTR)        // 10240
#define STAGE_ELEMS (A_ELEMS + B_ELEMS)
#define STAGE_BYTES (STAGE_ELEMS * 2)
#define SMEM_BYTES  (STAGE_BYTES * STAGES)    // 84480

#define SQH 264                    // bf16 stride (256 + 8 pad)

__device__ __nv_bfloat16 g_Xc[(size_t)MAXTILES * 96 * HID];  // compacted rows, bf16
__device__ __nv_bfloat16 g_Wb[(size_t)2048 * HID];
__device__ float g_contribH[(NHEAD / HPB) * NROWS];          // only j<len written; rest stay 0
__device__ int g_rowStart[NWIN];
__device__ int g_winList[NWIN];
__device__ int g_tileOff[6];
__device__ int g_winOff[6];
__device__ int g_nTiles;

__device__ __forceinline__ void cp16(uint32_t dst, const void* src) {
    asm volatile("cp.async.cg.shared.global [%0], [%1], 16;\n" :: "r"(dst), "l"(src));
}
__device__ __forceinline__ void cp_commit() {
    asm volatile("cp.async.commit_group;\n" ::: "memory");
}
__device__ __forceinline__ void ldsm_x4(uint32_t r[4], uint32_t addr) {
    asm volatile("ldmatrix.sync.aligned.m8n8.x4.shared.b16 {%0,%1,%2,%3}, [%4];"
                 : "=r"(r[0]), "=r"(r[1]), "=r"(r[2]), "=r"(r[3]) : "r"(addr));
}
__device__ __forceinline__ void mma_bf16(float c[4], uint32_t a0, uint32_t a1,
                                         uint32_t a2, uint32_t a3,
                                         uint32_t b0, uint32_t b1) {
    asm volatile(
        "mma.sync.aligned.m16n8k16.row.col.f32.bf16.bf16.f32 "
        "{%0,%1,%2,%3}, {%4,%5,%6,%7}, {%8,%9}, {%0,%1,%2,%3};\n"
        : "+f"(c[0]), "+f"(c[1]), "+f"(c[2]), "+f"(c[3])
        : "r"(a0), "r"(a1), "r"(a2), "r"(a3), "r"(b0), "r"(b1));
}

// ---------------------------------------------------------------------------
// Prepass: window lengths -> length buckets -> tile schedule + row placement.
// ---------------------------------------------------------------------------
__global__ void __launch_bounds__(256)
prepass_kernel(const int* __restrict__ idx) {
    __shared__ int cnt[5], base[5], toff[5], off[5];
    int tid = threadIdx.x;
    if (tid < 5) cnt[tid] = 0;
    __syncthreads();
    int lens[16];
#pragma unroll
    for (int t = 0; t < 16; t++) {
        int bw = tid * 16 + t;
        int L = 0;
#pragma unroll
        for (int k = 0; k < KSUB; k++) {
            int id = idx[bw * KSUB + k];
            if (id != 0 || (((bw & (WIN - 1)) == 0) && k == 0)) L++;
        }
        L = max(2, min(6, L));
        lens[t] = L;
        atomicAdd(&cnt[L - 2], 1);
    }
    __syncthreads();
    if (tid == 0) {
        int wacc = 0, tacc = 0;
        for (int b = 0; b < 5; b++) {
            int wpt = 96 / (b + 2);
            base[b] = wacc; toff[b] = tacc;
            g_winOff[b] = wacc; g_tileOff[b] = tacc;
            wacc += cnt[b];
            tacc += (cnt[b] + wpt - 1) / wpt;
            off[b] = base[b];
        }
        g_winOff[5] = wacc; g_tileOff[5] = tacc;
        g_nTiles = tacc;
    }
    __syncthreads();
#pragma unroll
    for (int t = 0; t < 16; t++) {
        int bw = tid * 16 + t;
        int L = lens[t];
        int b = L - 2;
        int wpt = 96 / L;
        int pos = atomicAdd(&off[b], 1);
        g_winList[pos] = bw;
        int p = pos - base[b];
        int tile = toff[b] + p / wpt;
        g_rowStart[bw] = tile * 96 + (p % wpt) * L;
    }
}

// ---------------------------------------------------------------------------
// Convert & permute W[:2048] -> g_Wb, row order [head][q(64)|k(64)].
// ---------------------------------------------------------------------------
__global__ void __launch_bounds__(256)
prep_w_kernel(const float* __restrict__ Wt) {
    int o = blockIdx.x;
    int t = threadIdx.x;
    int h = o >> 7;
    int r = o & 127;
    int src = ((r >= 64) ? HID : 0) + h * HD + (r & 63);
    float4 v = reinterpret_cast<const float4*>(Wt)[(size_t)src * 256 + t];
    __nv_bfloat162 lo = __floats2bfloat162_rn(v.x, v.y);
    __nv_bfloat162 hi = __floats2bfloat162_rn(v.z, v.w);
    uint2 pk;
    pk.x = *reinterpret_cast<uint32_t*>(&lo);
    pk.y = *reinterpret_cast<uint32_t*>(&hi);
    reinterpret_cast<uint2*>(g_Wb)[(size_t)o * 256 + t] = pk;
}

// ---------------------------------------------------------------------------
// Fused passthrough + gather (scatter covered rows into compacted g_Xc).
// ---------------------------------------------------------------------------
__global__ void __launch_bounds__(256)
fused_pass_kernel(const float* __restrict__ emb, const int* __restrict__ idx,
                  float* __restrict__ out) {
    int gid = blockIdx.x * 256 + threadIdx.x;   // float4 index
    int sg = gid >> 8;
    int s = sg & (SEQ - 1);
    int t = gid & 255;
    int k = s & 7;
    int bw = (sg >> 10) * WIN + (s >> 3);
    bool covered = false;
    if (k < KSUB) {
        int id = idx[bw * KSUB + k];
        covered = (id != 0) || (s == 0);
    }
    float4 v = reinterpret_cast<const float4*>(emb)[gid];
    float4 z = make_float4(0.f, 0.f, 0.f, 0.f);
    reinterpret_cast<float4*>(out)[gid] = covered ? z : v;
    if (covered) {
        int row = g_rowStart[bw] + k;
        __nv_bfloat162 lo = __floats2bfloat162_rn(v.x, v.y);
        __nv_bfloat162 hi = __floats2bfloat162_rn(v.z, v.w);
        uint2 pk;
        pk.x = *reinterpret_cast<uint32_t*>(&lo);
        pk.y = *reinterpret_cast<uint32_t*>(&hi);
        reinterpret_cast<uint2*>(g_Xc)[(size_t)row * 256 + t] = pk;
    }
}

// ---------------------------------------------------------------------------
// bf16 GEMM over compacted tiles + fused scores/softmax/contrib.
// grid = (264, 8), 256 threads, 2 blocks/SM.
// ---------------------------------------------------------------------------
__global__ void __launch_bounds__(256, 2)
gemm_scores_kernel(const float* __restrict__ bias) {
    extern __shared__ char smem_raw[];
    __nv_bfloat16* sQKh = reinterpret_cast<__nv_bfloat16*>(smem_raw); // [96][SQH]
    float* sAT = reinterpret_cast<float*>(smem_raw + MT * SQH * 2);   // [2*96][6]
    float* sBK = sAT + 2 * MT * KSUB;                                 // [2][64] k-bias

    const int tile = blockIdx.x;
    if (tile >= g_nTiles) return;
    const int by = blockIdx.y;
    const int tid = threadIdx.x;
    const int warp = tid >> 5;
    const int lane = tid & 31;
    const int g = lane >> 2;
    const int c = lane & 3;
    const int mw = warp >> 2;
    const int nw = warp & 3;

    // tile schedule
    int b = 0;
#pragma unroll
    for (int i = 1; i < 5; i++) if (tile >= g_tileOff[i]) b = i;
    const int L = b + 2;
    const int wpt = 96 / L;
    const int lt = tile - g_tileOff[b];
    const int winBase = g_winOff[b] + lt * wpt;
    const int bcnt = g_winOff[b + 1] - g_winOff[b];
    const int nwin = min(wpt, bcnt - lt * wpt);
    const int rows = nwin * L;

    const size_t arow0 = (size_t)tile * 96;
    const int wrow0 = by * NT;
    const uint32_t smem_u32 = (uint32_t)__cvta_generic_to_shared(smem_raw);

    const int ar = mw * 48 + ((lane >> 3) & 1) * 8 + (lane & 7);
    const int ac = (lane >> 4) * 8;
    const uint32_t a_off = (uint32_t)(ar * ASTR + ac) * 2;
    const int br = nw * 64 + ((lane >> 4) & 1) * 8 + (lane & 7);
    const int bc = ((lane >> 3) & 1) * 8;
    const uint32_t b_off = (uint32_t)A_ELEMS * 2 + (uint32_t)(br * BSTR + bc) * 2;

    float acc[3][8][4];
#pragma unroll
    for (int m = 0; m < 3; m++)
#pragma unroll
        for (int n = 0; n < 8; n++)
#pragma unroll
            for (int e = 0; e < 4; e++) acc[m][n][e] = 0.f;

    auto issue = [&](int s, int kk) {
        uint32_t base = smem_u32 + (uint32_t)(s % STAGES) * STAGE_BYTES;
        const __nv_bfloat16* asrc = g_Xc + arow0 * HID + kk;
        {
            int cA = tid;
            cp16(base + (cA >> 2) * (ASTR * 2) + (cA & 3) * 16,
                 asrc + (size_t)(cA >> 2) * HID + (cA & 3) * 8);
            if (tid < 128) {
                int c2 = tid + 256;
                cp16(base + (c2 >> 2) * (ASTR * 2) + (c2 & 3) * 16,
                     asrc + (size_t)(c2 >> 2) * HID + (c2 & 3) * 8);
            }
        }
        const __nv_bfloat16* bsrc = g_Wb + (size_t)wrow0 * HID + kk;
        uint32_t bbase = base + A_ELEMS * 2;
#pragma unroll
        for (int i = 0; i < 4; i++) {
            int cB = tid + i * 256;
            cp16(bbase + (cB >> 2) * (BSTR * 2) + (cB & 3) * 16,
                 bsrc + (size_t)(cB >> 2) * HID + (cB & 3) * 8);
        }
    };

    issue(0, 0); cp_commit();
    issue(1, KC); cp_commit();

    for (int it = 0; it < NKITER; ++it) {
        asm volatile("cp.async.wait_group 1;\n" ::: "memory");
        __syncthreads();
        if (it + 2 < NKITER) issue(it + 2, (it + 2) * KC);
        cp_commit();

        uint32_t stage_base = smem_u32 + (uint32_t)(it % STAGES) * STAGE_BYTES;
#pragma unroll
        for (int ks = 0; ks < 2; ks++) {
            const int kb = ks * 16;
            uint32_t a[3][4];
#pragma unroll
            for (int m = 0; m < 3; m++)
                ldsm_x4(a[m], stage_base + a_off + (uint32_t)(m * 16 * ASTR + kb) * 2);
#pragma unroll
            for (int np = 0; np < 4; np++) {
                uint32_t bfr[4];
                ldsm_x4(bfr, stage_base + b_off + (uint32_t)(np * 16 * BSTR + kb) * 2);
#pragma unroll
                for (int m = 0; m < 3; m++) {
                    mma_bf16(acc[m][np * 2 + 0], a[m][0], a[m][1], a[m][2], a[m][3],
                             bfr[0], bfr[1]);
                    mma_bf16(acc[m][np * 2 + 1], a[m][0], a[m][1], a[m][2], a[m][3],
                             bfr[2], bfr[3]);
                }
            }
        }
    }
    asm volatile("cp.async.wait_group 0;\n" ::: "memory");
    __syncthreads();

    // ---- epilogue: write QK tile (bias add, bf16) + stage k-bias ----
    const int hh = nw >> 1;
    const int qk = nw & 1;
#pragma unroll
    for (int m = 0; m < 3; m++)
#pragma unroll
        for (int n = 0; n < 8; n++) {
            int row = mw * 48 + m * 16 + g;
            int loc = n * 8 + c * 2;
            int col = hh * 128 + qk * 64 + loc;
            int bidx = (qk ? HID : 0) + (2 * by + hh) * HD + loc;
            float b0v = bias[bidx], b1v = bias[bidx + 1];
            *reinterpret_cast<__nv_bfloat162*>(sQKh + row * SQH + col) =
                __floats2bfloat162_rn(acc[m][n][0] + b0v, acc[m][n][1] + b1v);
            *reinterpret_cast<__nv_bfloat162*>(sQKh + (row + 8) * SQH + col) =
                __floats2bfloat162_rn(acc[m][n][2] + b0v, acc[m][n][3] + b1v);
        }
    if (tid < 128)
        sBK[tid] = bias[HID + (2 * by + (tid >> 6)) * HD + (tid & 63)];
    __syncthreads();

    // ---- scores + softmax over all 6 columns ----
    // Invalid columns (j >= L) have k-row == bias_k exactly (zeroed input row),
    // pair mask 0: score = q_i . bias_k / 8. They enter ONLY the denominator.
    if (tid < 2 * rows) {
        int h2 = tid / rows;
        int r = tid - h2 * rows;
        int wloc = r / L, i = r - wloc * L;
        int rbase = wloc * L;
        const __nv_bfloat162* qrow = reinterpret_cast<const __nv_bfloat162*>(
            sQKh + (rbase + i) * SQH + h2 * 128);
        const float* bk = sBK + h2 * 64;
        float sc[KSUB];
        float dinv = 0.f;
#pragma unroll
        for (int x = 0; x < HD / 2; x++) {
            float2 qv = __bfloat1622float2(qrow[x]);
            dinv += qv.x * bk[2 * x] + qv.y * bk[2 * x + 1];
        }
        dinv *= 0.125f;
#pragma unroll
        for (int j = 0; j < KSUB; j++) {
            if (j < L) {
                const __nv_bfloat162* krow = reinterpret_cast<const __nv_bfloat162*>(
                    sQKh + (rbase + j) * SQH + h2 * 128 + HD);
                float d = 0.f;
#pragma unroll
                for (int x = 0; x < HD / 2; x++) {
                    float2 qv = __bfloat1622float2(qrow[x]);
                    float2 kv = __bfloat1622float2(krow[x]);
                    d += qv.x * kv.x + qv.y * kv.y;
                }
                sc[j] = d * 0.125f + 1.0f;   // pair mask = 1 among valid rows
            } else sc[j] = dinv;
        }
        float mx = dinv;
#pragma unroll
        for (int j = 0; j < KSUB; j++) mx = fmaxf(mx, sc[j]);
        float ssum = 0.f;
        float e[KSUB];
#pragma unroll
        for (int j = 0; j < KSUB; j++) {
            e[j] = expf(sc[j] - mx);
            ssum += e[j];
        }
        float inv = 1.f / ssum;
#pragma unroll
        for (int j = 0; j < KSUB; j++)
            if (j < L) sAT[(h2 * MT + r) * KSUB + j] = e[j] * inv;
    }
    __syncthreads();

    // ---- contrib (both heads summed), * 1/NHEAD ----
    if (tid < rows) {
        int wloc = tid / L, j = tid - wloc * L;
        int rbase = wloc * L;
        float cv = 0.f;
#pragma unroll
        for (int h2 = 0; h2 < 2; h2++)
#pragma unroll
            for (int i2 = 0; i2 < KSUB; i2++)
                if (i2 < L) cv += sAT[(h2 * MT + rbase + i2) * KSUB + j];
        int bw = g_winList[winBase + wloc];
        g_contribH[(size_t)by * NROWS + bw * KSUB + j] = cv * (1.0f / (float)NHEAD);
    }
}

// ---------------------------------------------------------------------------
// Finalize: sum contrib over head-pairs (gated by validity), normalize,
// fp32 gather-weighted sum, scatter to out[b, w*8].
// ---------------------------------------------------------------------------
__global__ void __launch_bounds__(256)
finalize_kernel(const float* __restrict__ emb, const int* __restrict__ idx,
                float* __restrict__ out) {
    int bw = blockIdx.x;
    __shared__ float scon[KSUB];
    __shared__ int sid[KSUB];
    if (threadIdx.x < KSUB) {
        int base = bw * KSUB + threadIdx.x;
        int id = idx[base];
        bool vk = (id != 0) || (((bw & (WIN - 1)) == 0) && threadIdx.x == 0);
        float s = 0.f;
#pragma unroll
        for (int by = 0; by < NHEAD / HPB; by++) s += g_contribH[(size_t)by * NROWS + base];
        scon[threadIdx.x] = vk ? s : 0.f;
        sid[threadIdx.x] = vk ? id : 0;
    }
    __syncthreads();
    float sum = scon[0] + scon[1] + scon[2] + scon[3] + scon[4] + scon[5];
    float inv = 1.0f / (sum + 1e-8f);
    int t = threadIdx.x;
    int b = bw >> 7;
    float4 u = make_float4(0.f, 0.f, 0.f, 0.f);
#pragma unroll
    for (int k = 0; k < KSUB; k++) {
        float cw = scon[k] * inv;
        float4 v = reinterpret_cast<const float4*>(emb)[(size_t)(b * SEQ + sid[k]) * 256 + t];
        u.x += cw * v.x; u.y += cw * v.y; u.z += cw * v.z; u.w += cw * v.w;
    }
    int w = bw & (WIN - 1);
    reinterpret_cast<float4*>(out)[(size_t)(b * SEQ + w * 8) * 256 + t] = u;
}

// ---------------------------------------------------------------------------
extern "C" void kernel_launch(void* const* d_in, const int* in_sizes, int n_in,
                              void* d_out, int out_size) {
    const float* emb  = (const float*)d_in[0];
    const float* Wt   = (const float*)d_in[1];
    const float* bias = (const float*)d_in[2];
    const int* idx    = (const int*)d_in[3];
    float* out = (float*)d_out;
    (void)in_sizes; (void)n_in; (void)out_size;

    cudaFuncSetAttribute(gemm_scores_kernel,
                         cudaFuncAttributeMaxDynamicSharedMemorySize, SMEM_BYTES);

    prepass_kernel<<<1, 256>>>(idx);
    prep_w_kernel<<<2048, 256>>>(Wt);
    fused_pass_kernel<<<(BATCH * SEQ * HID / 4) / 256, 256>>>(emb, idx, out);
    gemm_scores_kernel<<<dim3(MAXTILES, NHEAD / HPB), 256, SMEM_BYTES>>>(bias);
    finalize_kernel<<<NWIN, 256>>>(emb, idx, out);
}

// round 15
// speedup vs baseline: 2.9135x; 1.0832x over previous
#include <cuda_runtime.h>
#include <cuda_bf16.h>
#include <cstdint>

// Problem constants
#define BATCH 32
#define SEQ   1024
#define HID   1024
#define WIN   128
#define KSUB  6
#define NHEAD 16
#define HD    64
#define NWIN  (BATCH * WIN)        // 4096
#define NROWS (NWIN * KSUB)        // 24576

// GEMM tiling: 96 compacted rows (variable #windows) x 2 heads (N=256)
#define HPB 2
#define MT 96
#define NT (HPB * 128)
#define KC 64                      // k per stage (128 B rows)
#define STAGES 2
#define NKITER (HID / KC)          // 16
#define MAXTILES 264

#define ASTR 72                    // bf16 elems per A row in smem (64 + 8 pad)
#define BSTR 72
#define A_ELEMS (MT * ASTR)        // 6912
#define B_ELEMS (NT * BSTR)        // 18432
#define STAGE_ELEMS (A_ELEMS + B_ELEMS)       // 25344
#define STAGE_BYTES (STAGE_ELEMS * 2)         // 50688
#define SMEM_BYTES  (STAGE_BYTES * STAGES)    // 101376

#define SQH 264                    // bf16 stride (256 + 8 pad)

__device__ __nv_bfloat16 g_Xc[(size_t)MAXTILES * 96 * HID];  // compacted rows, bf16
__device__ __nv_bfloat16 g_Wb[(size_t)2048 * HID];
__device__ float g_contribH[(NHEAD / HPB) * NROWS];          // only j<len written; rest stay 0
__device__ int g_rowStart[NWIN];
__device__ int g_winList[NWIN];
__device__ int g_tileOff[6];
__device__ int g_winOff[6];
__device__ int g_nTiles;

__device__ __forceinline__ void cp16(uint32_t dst, const void* src) {
    asm volatile("cp.async.cg.shared.global [%0], [%1], 16;\n" :: "r"(dst), "l"(src));
}
__device__ __forceinline__ void cp_commit() {
    asm volatile("cp.async.commit_group;\n" ::: "memory");
}
__device__ __forceinline__ void ldsm_x4(uint32_t r[4], uint32_t addr) {
    asm volatile("ldmatrix.sync.aligned.m8n8.x4.shared.b16 {%0,%1,%2,%3}, [%4];"
                 : "=r"(r[0]), "=r"(r[1]), "=r"(r[2]), "=r"(r[3]) : "r"(addr));
}
__device__ __forceinline__ void mma_bf16(float c[4], uint32_t a0, uint32_t a1,
                                         uint32_t a2, uint32_t a3,
                                         uint32_t b0, uint32_t b1) {
    asm volatile(
        "mma.sync.aligned.m16n8k16.row.col.f32.bf16.bf16.f32 "
        "{%0,%1,%2,%3}, {%4,%5,%6,%7}, {%8,%9}, {%0,%1,%2,%3};\n"
        : "+f"(c[0]), "+f"(c[1]), "+f"(c[2]), "+f"(c[3])
        : "r"(a0), "r"(a1), "r"(a2), "r"(a3), "r"(b0), "r"(b1));
}

// ---------------------------------------------------------------------------
// Prepass: window lengths -> length buckets -> tile schedule + row placement.
// ---------------------------------------------------------------------------
__global__ void __launch_bounds__(256)
prepass_kernel(const int* __restrict__ idx) {
    __shared__ int cnt[5], base[5], toff[5], off[5];
    int tid = threadIdx.x;
    if (tid < 5) cnt[tid] = 0;
    __syncthreads();
    int lens[16];
#pragma unroll
    for (int t = 0; t < 16; t++) {
        int bw = tid * 16 + t;
        int L = 0;
#pragma unroll
        for (int k = 0; k < KSUB; k++) {
            int id = idx[bw * KSUB + k];
            if (id != 0 || (((bw & (WIN - 1)) == 0) && k == 0)) L++;
        }
        L = max(2, min(6, L));
        lens[t] = L;
        atomicAdd(&cnt[L - 2], 1);
    }
    __syncthreads();
    if (tid == 0) {
        int wacc = 0, tacc = 0;
        for (int b = 0; b < 5; b++) {
            int wpt = 96 / (b + 2);
            base[b] = wacc; toff[b] = tacc;
            g_winOff[b] = wacc; g_tileOff[b] = tacc;
            wacc += cnt[b];
            tacc += (cnt[b] + wpt - 1) / wpt;
            off[b] = base[b];
        }
        g_winOff[5] = wacc; g_tileOff[5] = tacc;
        g_nTiles = tacc;
    }
    __syncthreads();
#pragma unroll
    for (int t = 0; t < 16; t++) {
        int bw = tid * 16 + t;
        int L = lens[t];
        int b = L - 2;
        int wpt = 96 / L;
        int pos = atomicAdd(&off[b], 1);
        g_winList[pos] = bw;
        int p = pos - base[b];
        int tile = toff[b] + p / wpt;
        g_rowStart[bw] = tile * 96 + (p % wpt) * L;
    }
}

// ---------------------------------------------------------------------------
// Convert & permute W[:2048] -> g_Wb, row order [head][q(64)|k(64)].
// ---------------------------------------------------------------------------
__global__ void __launch_bounds__(256)
prep_w_kernel(const float* __restrict__ Wt) {
    int o = blockIdx.x;
    int t = threadIdx.x;
    int h = o >> 7;
    int r = o & 127;
    int src = ((r >= 64) ? HID : 0) + h * HD + (r & 63);
    float4 v = reinterpret_cast<const float4*>(Wt)[(size_t)src * 256 + t];
    __nv_bfloat162 lo = __floats2bfloat162_rn(v.x, v.y);
    __nv_bfloat162 hi = __floats2bfloat162_rn(v.z, v.w);
    uint2 pk;
    pk.x = *reinterpret_cast<uint32_t*>(&lo);
    pk.y = *reinterpret_cast<uint32_t*>(&hi);
    reinterpret_cast<uint2*>(g_Wb)[(size_t)o * 256 + t] = pk;
}

// ---------------------------------------------------------------------------
// Fused passthrough + gather (scatter covered rows into compacted g_Xc).
// ---------------------------------------------------------------------------
__global__ void __launch_bounds__(256)
fused_pass_kernel(const float* __restrict__ emb, const int* __restrict__ idx,
                  float* __restrict__ out) {
    int gid = blockIdx.x * 256 + threadIdx.x;   // float4 index
    int sg = gid >> 8;
    int s = sg & (SEQ - 1);
    int t = gid & 255;
    int k = s & 7;
    int bw = (sg >> 10) * WIN + (s >> 3);
    bool covered = false;
    if (k < KSUB) {
        int id = idx[bw * KSUB + k];
        covered = (id != 0) || (s == 0);
    }
    float4 v = reinterpret_cast<const float4*>(emb)[gid];
    float4 z = make_float4(0.f, 0.f, 0.f, 0.f);
    reinterpret_cast<float4*>(out)[gid] = covered ? z : v;
    if (covered) {
        int row = g_rowStart[bw] + k;
        __nv_bfloat162 lo = __floats2bfloat162_rn(v.x, v.y);
        __nv_bfloat162 hi = __floats2bfloat162_rn(v.z, v.w);
        uint2 pk;
        pk.x = *reinterpret_cast<uint32_t*>(&lo);
        pk.y = *reinterpret_cast<uint32_t*>(&hi);
        reinterpret_cast<uint2*>(g_Xc)[(size_t)row * 256 + t] = pk;
    }
}

// ---------------------------------------------------------------------------
// bf16 GEMM over compacted tiles + fused scores/softmax/contrib.
// grid = (264, 8), 256 threads, 2 blocks/SM.
// ---------------------------------------------------------------------------
__global__ void __launch_bounds__(256, 2)
gemm_scores_kernel(const float* __restrict__ bias) {
    extern __shared__ char smem_raw[];
    __nv_bfloat16* sQKh = reinterpret_cast<__nv_bfloat16*>(smem_raw); // [96][SQH]
    float* sAT = reinterpret_cast<float*>(smem_raw + MT * SQH * 2);   // [2*96][6]
    float* sBK = sAT + 2 * MT * KSUB;                                 // [2][64] k-bias

    const int tile = blockIdx.x;
    if (tile >= g_nTiles) return;
    const int by = blockIdx.y;
    const int tid = threadIdx.x;
    const int warp = tid >> 5;
    const int lane = tid & 31;
    const int g = lane >> 2;
    const int c = lane & 3;
    const int mw = warp >> 2;
    const int nw = warp & 3;

    // tile schedule
    int b = 0;
#pragma unroll
    for (int i = 1; i < 5; i++) if (tile >= g_tileOff[i]) b = i;
    const int L = b + 2;
    const int wpt = 96 / L;
    const int lt = tile - g_tileOff[b];
    const int winBase = g_winOff[b] + lt * wpt;
    const int bcnt = g_winOff[b + 1] - g_winOff[b];
    const int nwin = min(wpt, bcnt - lt * wpt);
    const int rows = nwin * L;

    const size_t arow0 = (size_t)tile * 96;
    const int wrow0 = by * NT;
    const uint32_t smem_u32 = (uint32_t)__cvta_generic_to_shared(smem_raw);

    const int ar = mw * 48 + ((lane >> 3) & 1) * 8 + (lane & 7);
    const int ac = (lane >> 4) * 8;
    const uint32_t a_off = (uint32_t)(ar * ASTR + ac) * 2;
    const int br = nw * 64 + ((lane >> 4) & 1) * 8 + (lane & 7);
    const int bc = ((lane >> 3) & 1) * 8;
    const uint32_t b_off = (uint32_t)A_ELEMS * 2 + (uint32_t)(br * BSTR + bc) * 2;

    float acc[3][8][4];
#pragma unroll
    for (int m = 0; m < 3; m++)
#pragma unroll
        for (int n = 0; n < 8; n++)
#pragma unroll
            for (int e = 0; e < 4; e++) acc[m][n][e] = 0.f;

    // KC=64 stage: A = 96 rows x 128 B (768 x 16B chunks, 3/thread),
    //              B = 256 rows x 128 B (2048 chunks, 8/thread)
    auto issue = [&](int s, int kk) {
        uint32_t base = smem_u32 + (uint32_t)(s & 1) * STAGE_BYTES;
        const __nv_bfloat16* asrc = g_Xc + arow0 * HID + kk;
#pragma unroll
        for (int t = 0; t < 3; t++) {
            int i = tid + t * 256;
            int r = i >> 3, cc = i & 7;
            cp16(base + r * (ASTR * 2) + cc * 16, asrc + (size_t)r * HID + cc * 8);
        }
        const __nv_bfloat16* bsrc = g_Wb + (size_t)wrow0 * HID + kk;
        uint32_t bbase = base + A_ELEMS * 2;
#pragma unroll
        for (int t = 0; t < 8; t++) {
            int i = tid + t * 256;
            int r = i >> 3, cc = i & 7;
            cp16(bbase + r * (BSTR * 2) + cc * 16, bsrc + (size_t)r * HID + cc * 8);
        }
    };

    issue(0, 0); cp_commit();

    for (int it = 0; it < NKITER; ++it) {
        asm volatile("cp.async.wait_group 0;\n" ::: "memory");
        __syncthreads();
        if (it + 1 < NKITER) { issue(it + 1, (it + 1) * KC); cp_commit(); }

        uint32_t stage_base = smem_u32 + (uint32_t)(it & 1) * STAGE_BYTES;
#pragma unroll
        for (int ks = 0; ks < 4; ks++) {
            const int kb = ks * 16;
            uint32_t a[3][4];
#pragma unroll
            for (int m = 0; m < 3; m++)
                ldsm_x4(a[m], stage_base + a_off + (uint32_t)(m * 16 * ASTR + kb) * 2);
#pragma unroll
            for (int np = 0; np < 4; np++) {
                uint32_t bfr[4];
                ldsm_x4(bfr, stage_base + b_off + (uint32_t)(np * 16 * BSTR + kb) * 2);
#pragma unroll
                for (int m = 0; m < 3; m++) {
                    mma_bf16(acc[m][np * 2 + 0], a[m][0], a[m][1], a[m][2], a[m][3],
                             bfr[0], bfr[1]);
                    mma_bf16(acc[m][np * 2 + 1], a[m][0], a[m][1], a[m][2], a[m][3],
                             bfr[2], bfr[3]);
                }
            }
        }
    }
    __syncthreads();

    // ---- epilogue: write QK tile (bias add, bf16) + stage k-bias ----
    const int hh = nw >> 1;
    const int qk = nw & 1;
#pragma unroll
    for (int m = 0; m < 3; m++)
#pragma unroll
        for (int n = 0; n < 8; n++) {
            int row = mw * 48 + m * 16 + g;
            int loc = n * 8 + c * 2;
            int col = hh * 128 + qk * 64 + loc;
            int bidx = (qk ? HID : 0) + (2 * by + hh) * HD + loc;
            float b0v = bias[bidx], b1v = bias[bidx + 1];
            *reinterpret_cast<__nv_bfloat162*>(sQKh + row * SQH + col) =
                __floats2bfloat162_rn(acc[m][n][0] + b0v, acc[m][n][1] + b1v);
            *reinterpret_cast<__nv_bfloat162*>(sQKh + (row + 8) * SQH + col) =
                __floats2bfloat162_rn(acc[m][n][2] + b0v, acc[m][n][3] + b1v);
        }
    if (tid < 128)
        sBK[tid] = bias[HID + (2 * by + (tid >> 6)) * HD + (tid & 63)];
    __syncthreads();

    // ---- scores + softmax over all 6 columns ----
    // Invalid columns (j >= L) have k-row == bias_k exactly (zeroed input row),
    // pair mask 0: score = q_i . bias_k / 8. They enter ONLY the denominator.
    if (tid < 2 * rows) {
        int h2 = tid / rows;
        int r = tid - h2 * rows;
        int wloc = r / L, i = r - wloc * L;
        int rbase = wloc * L;
        const __nv_bfloat162* qrow = reinterpret_cast<const __nv_bfloat162*>(
            sQKh + (rbase + i) * SQH + h2 * 128);
        const float* bk = sBK + h2 * 64;
        float sc[KSUB];
        float dinv = 0.f;
#pragma unroll
        for (int x = 0; x < HD / 2; x++) {
            float2 qv = __bfloat1622float2(qrow[x]);
            dinv += qv.x * bk[2 * x] + qv.y * bk[2 * x + 1];
        }
        dinv *= 0.125f;
#pragma unroll
        for (int j = 0; j < KSUB; j++) {
            if (j < L) {
                const __nv_bfloat162* krow = reinterpret_cast<const __nv_bfloat162*>(
                    sQKh + (rbase + j) * SQH + h2 * 128 + HD);
                float d = 0.f;
#pragma unroll
                for (int x = 0; x < HD / 2; x++) {
                    float2 qv = __bfloat1622float2(qrow[x]);
                    float2 kv = __bfloat1622float2(krow[x]);
                    d += qv.x * kv.x + qv.y * kv.y;
                }
                sc[j] = d * 0.125f + 1.0f;   // pair mask = 1 among valid rows
            } else sc[j] = dinv;
        }
        float mx = dinv;
#pragma unroll
        for (int j = 0; j < KSUB; j++) mx = fmaxf(mx, sc[j]);
        float ssum = 0.f;
        float e[KSUB];
#pragma unroll
        for (int j = 0; j < KSUB; j++) {
            e[j] = expf(sc[j] - mx);
            ssum += e[j];
        }
        float inv = 1.f / ssum;
#pragma unroll
        for (int j = 0; j < KSUB; j++)
            if (j < L) sAT[(h2 * MT + r) * KSUB + j] = e[j] * inv;
    }
    __syncthreads();

    // ---- contrib (both heads summed), * 1/NHEAD ----
    if (tid < rows) {
        int wloc = tid / L, j = tid - wloc * L;
        int rbase = wloc * L;
        float cv = 0.f;
#pragma unroll
        for (int h2 = 0; h2 < 2; h2++)
#pragma unroll
            for (int i2 = 0; i2 < KSUB; i2++)
                if (i2 < L) cv += sAT[(h2 * MT + rbase + i2) * KSUB + j];
        int bw = g_winList[winBase + wloc];
        g_contribH[(size_t)by * NROWS + bw * KSUB + j] = cv * (1.0f / (float)NHEAD);
    }
}

// ---------------------------------------------------------------------------
// Finalize: sum contrib over head-pairs (gated by validity), normalize,
// fp32 gather-weighted sum, scatter to out[b, w*8].
// ---------------------------------------------------------------------------
__global__ void __launch_bounds__(256)
finalize_kernel(const float* __restrict__ emb, const int* __restrict__ idx,
                float* __restrict__ out) {
    int bw = blockIdx.x;
    __shared__ float scon[KSUB];
    __shared__ int sid[KSUB];
    if (threadIdx.x < KSUB) {
        int base = bw * KSUB + threadIdx.x;
        int id = idx[base];
        bool vk = (id != 0) || (((bw & (WIN - 1)) == 0) && threadIdx.x == 0);
        float s = 0.f;
#pragma unroll
        for (int by = 0; by < NHEAD / HPB; by++) s += g_contribH[(size_t)by * NROWS + base];
        scon[threadIdx.x] = vk ? s : 0.f;
        sid[threadIdx.x] = vk ? id : 0;
    }
    __syncthreads();
    float sum = scon[0] + scon[1] + scon[2] + scon[3] + scon[4] + scon[5];
    float inv = 1.0f / (sum + 1e-8f);
    int t = threadIdx.x;
    int b = bw >> 7;
    float4 u = make_float4(0.f, 0.f, 0.f, 0.f);
#pragma unroll
    for (int k = 0; k < KSUB; k++) {
        float cw = scon[k] * inv;
        float4 v = reinterpret_cast<const float4*>(emb)[(size_t)(b * SEQ + sid[k]) * 256 + t];
        u.x += cw * v.x; u.y += cw * v.y; u.z += cw * v.z; u.w += cw * v.w;
    }
    int w = bw & (WIN - 1);
    reinterpret_cast<float4*>(out)[(size_t)(b * SEQ + w * 8) * 256 + t] = u;
}

// ---------------------------------------------------------------------------
extern "C" void kernel_launch(void* const* d_in, const int* in_sizes, int n_in,
                              void* d_out, int out_size) {
    const float* emb  = (const float*)d_in[0];
    const float* Wt   = (const float*)d_in[1];
    const float* bias = (const float*)d_in[2];
    const int* idx    = (const int*)d_in[3];
    float* out = (float*)d_out;
    (void)in_sizes; (void)n_in; (void)out_size;

    cudaFuncSetAttribute(gemm_scores_kernel,
                         cudaFuncAttributeMaxDynamicSharedMemorySize, SMEM_BYTES);

    prepass_kernel<<<1, 256>>>(idx);
    prep_w_kernel<<<2048, 256>>>(Wt);
    fused_pass_kernel<<<(BATCH * SEQ * HID / 4) / 256, 256>>>(emb, idx, out);
    gemm_scores_kernel<<<dim3(MAXTILES, NHEAD / HPB), 256, SMEM_BYTES>>>(bias);
    finalize_kernel<<<NWIN, 256>>>(emb, idx, out);
}